// round 9
// baseline (speedup 1.0000x reference)
#include <cuda_runtime.h>
#include <cuda_bf16.h>
#include <math.h>
#include <cstdint>

#define B_ 16
#define T_ 512
#define IDIM_ 320
#define CD_ 1024
#define GD_ 4096   // 4*CD
#define HD_ 1024
#define LAYERS_ 4
#define NBLK_ 128  // persistent grid: <= 148 SMs -> all co-resident

typedef unsigned long long ull;
typedef unsigned int uint;
typedef signed char s8;   // aarch64: plain char is unsigned!

// ---------------- scratch (static device globals; no runtime alloc) ----------------
__device__ float g_xg[(size_t)B_ * T_ * GD_];      // precomputed input gates
__device__ float g_hT[CD_ * B_];                   // h transposed: hT[cell][b]
__device__ ull   g_bar;                            // ticket barrier (monotonic)
__device__ __align__(16) s8 g_qah[(size_t)B_ * T_ * CD_];  // A int8 hi
__device__ __align__(16) s8 g_qal[(size_t)B_ * T_ * CD_];  // A int8 lo
__device__ __align__(16) s8 g_qbh[(size_t)GD_ * CD_];      // B int8 hi
__device__ __align__(16) s8 g_qbl[(size_t)GD_ * CD_];      // B int8 lo
__device__ float g_sa[B_ * T_];                    // per-row A scale
__device__ float g_sb[GD_];                        // per-row B scale

// ---------------- packed fp32x2 helpers (step kernel) ----------------
__device__ __forceinline__ ull fma2(ull a, ull b, ull c) {
    ull d;
    asm("fma.rn.f32x2 %0, %1, %2, %3;" : "=l"(d) : "l"(a), "l"(b), "l"(c));
    return d;
}
__device__ __forceinline__ ull add2(ull a, ull b) {
    ull d;
    asm("add.rn.f32x2 %0, %1, %2;" : "=l"(d) : "l"(a), "l"(b));
    return d;
}
__device__ __forceinline__ ull pack2(float x, float y) {
    ull d;
    asm("mov.b64 %0, {%1, %2};" : "=l"(d) : "f"(x), "f"(y));
    return d;
}
__device__ __forceinline__ float2 unpack2(ull v) {
    float2 r;
    asm("mov.b64 {%0, %1}, %2;" : "=f"(r.x), "=f"(r.y) : "l"(v));
    return r;
}
__device__ __forceinline__ float sigf(float x) { return 1.f / (1.f + expf(-x)); }

#define HSTRIDE 20   // padded row stride (floats) for transposed h in smem

// ---------------- per-row int8 hi/lo quantization ----------------
// x row -> s = max|x|/127; qh = rint(x/s) in [-127,127]; ql = rint((x/s - qh)*128).
__global__ void __launch_bounds__(128) quant_rows_kernel(
    const float* __restrict__ x, s8* __restrict__ qh, s8* __restrict__ ql,
    float* __restrict__ sc, int K)
{
    __shared__ float wmax[4];
    const int row = blockIdx.x;
    const int tid = threadIdx.x;
    const float* xr = x + (size_t)row * K;
    float mx = 0.f;
    for (int i = tid; i < K; i += 128) mx = fmaxf(mx, fabsf(xr[i]));
#pragma unroll
    for (int off = 16; off >= 1; off >>= 1)
        mx = fmaxf(mx, __shfl_xor_sync(0xffffffffu, mx, off));
    if ((tid & 31) == 0) wmax[tid >> 5] = mx;
    __syncthreads();
    mx = fmaxf(fmaxf(wmax[0], wmax[1]), fmaxf(wmax[2], wmax[3]));
    const float s   = (mx > 0.f) ? mx / 127.f : 1.f;
    const float inv = (mx > 0.f) ? 127.f / mx : 0.f;
    if (tid == 0) sc[row] = s;
    for (int i = tid; i < K; i += 128) {
        const float q  = xr[i] * inv;
        const float qr = rintf(q);
        qh[(size_t)row * K + i] = (s8)qr;
        ql[(size_t)row * K + i] = (s8)rintf((q - qr) * 128.f);
    }
}

// fill A-scale with fixed 1/127 (h layers; |h| < 1)
__global__ void __launch_bounds__(256) fill_sa_kernel(float* __restrict__ sa) {
    sa[blockIdx.x * 256 + threadIdx.x] = 1.f / 127.f;
}

// ---------------- MMA helpers ----------------
__device__ __forceinline__ uint32_t smem_u32(const void* p) {
    uint32_t a;
    asm("{ .reg .u64 t; cvta.to.shared.u64 t, %1; cvt.u32.u64 %0, t; }" : "=r"(a) : "l"(p));
    return a;
}
__device__ __forceinline__ void ldmx4(uint& r0, uint& r1, uint& r2, uint& r3,
                                      uint32_t a) {
    asm volatile("ldmatrix.sync.aligned.m8n8.x4.shared.b16 {%0,%1,%2,%3}, [%4];"
                 : "=r"(r0), "=r"(r1), "=r"(r2), "=r"(r3) : "r"(a));
}
__device__ __forceinline__ void mma16832(int* d, const uint* a, uint b0, uint b1) {
    asm volatile(
        "mma.sync.aligned.m16n8k32.row.col.s32.s8.s8.s32 "
        "{%0,%1,%2,%3}, {%4,%5,%6,%7}, {%8,%9}, {%0,%1,%2,%3};"
        : "+r"(d[0]), "+r"(d[1]), "+r"(d[2]), "+r"(d[3])
        : "r"(a[0]), "r"(a[1]), "r"(a[2]), "r"(a[3]), "r"(b0), "r"(b1));
}

// ---------------- int8x3 GEMM (NT): C = sa*sb*(P0 + P1/128) + bias ----------------
// Block tile 128x128, BK=64 (two k32 mma steps), 256 threads, 8 warps (4M x 2N,
// warp tile 32x64). Register-prefetch ping-pong smem, ONE sync per slab.
// Segments: s in [0,perseg): Ah*Bh -> acc0; [perseg,2p): Al*Bh -> acc1;
//           [2p,3p): Ah*Bl -> acc1 (exact s32 accumulation).
// Dead rows (t >= ilens[b]): TANH=0 skip tile; TANH=1 output tanh(bias).
// Smem: 2 stages x (A 128x80B + B 128x80B) = 40960.
#define GSMEM 40960

#define DO_KH(ACC, KH) do {                                                   \
    const uint32_t cq_ = (KH) * 32 + ((lane >> 4) << 4);                      \
    uint af_[2][4];                                                           \
    ldmx4(af_[0][0], af_[0][1], af_[0][2], af_[0][3],                         \
          abase + (wm * 32 +  0 + rq) * 80 + cq_);                            \
    ldmx4(af_[1][0], af_[1][1], af_[1][2], af_[1][3],                         \
          abase + (wm * 32 + 16 + rq) * 80 + cq_);                            \
    _Pragma("unroll")                                                         \
    for (int nq_ = 0; nq_ < 4; ++nq_) {                                       \
        uint b0_, b1_, b2_, b3_;                                              \
        ldmx4(b0_, b1_, b2_, b3_, bbase + (wn * 64 + nq_ * 16 + rq) * 80 + cq_); \
        mma16832(ACC[0][2 * nq_],     af_[0], b0_, b2_);                      \
        mma16832(ACC[0][2 * nq_ + 1], af_[0], b1_, b3_);                      \
        mma16832(ACC[1][2 * nq_],     af_[1], b0_, b2_);                      \
        mma16832(ACC[1][2 * nq_ + 1], af_[1], b1_, b3_);                      \
    }                                                                         \
} while (0)

template <int TANH>
__global__ void __launch_bounds__(256) gemm_i8x3_kernel(
    const s8* __restrict__ Aqh, const s8* __restrict__ Aql,
    const s8* __restrict__ Bqh, const s8* __restrict__ Bql,
    const float* __restrict__ saA, const float* __restrict__ saB,
    const float* __restrict__ b1, const float* __restrict__ b2,
    float* __restrict__ C, int M, int N, int K, const int* __restrict__ ilens)
{
    extern __shared__ char smem[];
    const uint32_t sb = smem_u32(smem);

    const int tid  = threadIdx.x;
    const int lane = tid & 31;
    const int warp = tid >> 5;       // 0..7
    const int wm   = warp & 3;       // 4 warps along M
    const int wn   = warp >> 2;      // 2 warps along N
    const int m0 = blockIdx.y * 128;
    const int n0 = blockIdx.x * 128;

    const int ilb = __ldg(ilens + (m0 >> 9));
    const bool tdead = (m0 & 511) >= ilb;
    if (!TANH && tdead) return;

    int acc0[2][8][4];   // P0 = Ah*Bh
    int acc1[2][8][4];   // P1 = Al*Bh + Ah*Bl
#pragma unroll
    for (int i = 0; i < 2; ++i)
#pragma unroll
        for (int j = 0; j < 8; ++j)
#pragma unroll
            for (int q = 0; q < 4; ++q) { acc0[i][j][q] = 0; acc1[i][j][q] = 0; }

    if (!tdead) {
        const int perseg = K >> 6;        // 64-byte slabs per segment
        const int nslab  = 3 * perseg;

        const int srow  = tid >> 1;       // 0..127
        const int sbyte = (tid & 1) * 32; // 0 or 32

        uint4 pa0, pa1, pb0, pb1;
        auto loadAB = [&](int s) {
            const int seg = s / perseg;
            const int kin = (s - seg * perseg) * 64;
            const s8* Aseg = (seg == 1) ? Aql : Aqh;
            const s8* Bseg = (seg == 2) ? Bql : Bqh;
            const s8* ga = Aseg + (size_t)(m0 + srow) * K + kin + sbyte;
            const s8* gb = Bseg + (size_t)(n0 + srow) * K + kin + sbyte;
            pa0 = *(const uint4*)ga;
            pa1 = *(const uint4*)(ga + 16);
            pb0 = *(const uint4*)gb;
            pb1 = *(const uint4*)(gb + 16);
        };
        auto storeAB = [&](int buf) {
            char* ap = smem + buf * 20480 + srow * 80 + sbyte;
            *(uint4*)ap        = pa0;
            *(uint4*)(ap + 16) = pa1;
            char* bp = smem + buf * 20480 + 10240 + srow * 80 + sbyte;
            *(uint4*)bp        = pb0;
            *(uint4*)(bp + 16) = pb1;
        };

        loadAB(0);
        storeAB(0);
        __syncthreads();

        int buf = 0;
        const int rq = lane & 15;
        for (int s = 0; s < nslab; ++s) {
            if (s + 1 < nslab) loadAB(s + 1);

            const uint32_t abase = sb + buf * 20480;
            const uint32_t bbase = abase + 10240;
            if (s < perseg) {
                DO_KH(acc0, 0);
                DO_KH(acc0, 1);
            } else {
                DO_KH(acc1, 0);
                DO_KH(acc1, 1);
            }

            if (s + 1 < nslab) {
                storeAB(buf ^ 1);
                __syncthreads();
                buf ^= 1;
            }
        }
    }

    // epilogue: lane l holds c[r + {0,8}][c + {0,1}], r = l>>2, c = 2*(l&3)
    const int r   = lane >> 2;
    const int cq2 = (lane & 3) * 2;
#pragma unroll
    for (int mi = 0; mi < 2; ++mi) {
        const int m1 = m0 + wm * 32 + mi * 16 + r;
        const float sA0 = __ldg(saA + m1);
        const float sA8 = __ldg(saA + m1 + 8);
#pragma unroll
        for (int nj = 0; nj < 8; ++nj) {
            const int n1 = n0 + wn * 64 + nj * 8 + cq2;
            const float sB0 = __ldg(saB + n1);
            const float sB1 = __ldg(saB + n1 + 1);
            float bb0 = b1 ? __ldg(b1 + n1) : 0.f;
            float bb1 = b1 ? __ldg(b1 + n1 + 1) : 0.f;
            if (b2) { bb0 += __ldg(b2 + n1); bb1 += __ldg(b2 + n1 + 1); }
            float v0 = sA0 * sB0 * ((float)acc0[mi][nj][0] + 0.0078125f * (float)acc1[mi][nj][0]) + bb0;
            float v1 = sA0 * sB1 * ((float)acc0[mi][nj][1] + 0.0078125f * (float)acc1[mi][nj][1]) + bb1;
            float v2 = sA8 * sB0 * ((float)acc0[mi][nj][2] + 0.0078125f * (float)acc1[mi][nj][2]) + bb0;
            float v3 = sA8 * sB1 * ((float)acc0[mi][nj][3] + 0.0078125f * (float)acc1[mi][nj][3]) + bb1;
            if (TANH) {
                const bool d0 = tdead || ((m1 & 511) >= ilb);
                const bool d8 = tdead || (((m1 + 8) & 511) >= ilb);
                v0 = tanhf(d0 ? bb0 : v0);
                v1 = tanhf(d0 ? bb1 : v1);
                v2 = tanhf(d8 ? bb0 : v2);
                v3 = tanhf(d8 ? bb1 : v3);
            }
            *(float2*)(C + (size_t)m1 * N + n1)       = make_float2(v0, v1);
            *(float2*)(C + (size_t)(m1 + 8) * N + n1) = make_float2(v2, v3);
        }
    }
}

// ---------------- persistent LSTM layer kernel (512 threads, k-split warps) ----------------
// Emits h quantized int8 hi/lo directly (fixed scale 1/127); fp32 h kept in hT.
__global__ void __launch_bounds__(512) lstm_layer_kernel(
    const float* __restrict__ Whh,   // [4096,1024]
    const float* __restrict__ xg,    // [B*T,4096]
    s8* __restrict__ yh,             // [B*T,1024] h int8 hi
    s8* __restrict__ yl,             // [B*T,1024] h int8 lo
    float* __restrict__ hT)          // [1024,16]
{
    extern __shared__ float hs[];                    // [1024][HSTRIDE]
    ull* comb = (ull*)(hs + CD_ * HSTRIDE);          // [8*32] flat
    const int tid  = threadIdx.x;
    const int lane = tid & 31;
    const int warp = tid >> 5;                       // 0..15
    const int wc   = warp & 7;
    const int kh   = warp >> 3;
    const int cell = blockIdx.x * 8 + wc;
    const ull  G   = (ull)gridDim.x;

    const int koff = kh * 512;
    const float* w0p = Whh + (size_t)(0 * CD_ + cell) * CD_ + koff;
    const float* w1p = Whh + (size_t)(1 * CD_ + cell) * CD_ + koff;
    const float* w2p = Whh + (size_t)(2 * CD_ + cell) * CD_ + koff;
    const float* w3p = Whh + (size_t)(3 * CD_ + cell) * CD_ + koff;

    float creg = 0.f;

    for (int t = 0; t < T_; ++t) {
        float xgi = 0.f, xgf = 0.f, xgg = 0.f, xgo = 0.f;
        size_t orow = 0;
        if (kh == 0 && lane < B_) {
            orow = (size_t)(lane * T_ + t);
            const float* xr = xg + orow * GD_ + cell;
            xgi = __ldg(xr);
            xgf = __ldg(xr + CD_);
            xgg = __ldg(xr + 2 * CD_);
            xgo = __ldg(xr + 3 * CD_);
        }

        ull acc[32];
#pragma unroll
        for (int i = 0; i < 32; ++i) acc[i] = 0ULL;

        if (t > 0) {
            const float4* src = (const float4*)hT;
#pragma unroll 4
            for (int i = tid; i < CD_ * B_ / 4; i += 512) {
                float4 v = __ldcg(src + i);
                const int k  = i >> 2;
                const int bq = (i & 3) * 4;
                float* d = hs + k * HSTRIDE + bq;
                d[0] = v.x; d[1] = v.y; d[2] = v.z; d[3] = v.w;
            }
            __syncthreads();

#pragma unroll 1
            for (int j = 0; j < 4; ++j) {
                const int kb = j * 128 + lane;
#pragma unroll
                for (int kc = 0; kc < 4; ++kc) {
                    const int kk = kb + kc * 32;
                    const float w0 = __ldg(w0p + kk);
                    const float w1 = __ldg(w1p + kk);
                    const float w2 = __ldg(w2p + kk);
                    const float w3 = __ldg(w3p + kk);
                    const ull wp0 = pack2(w0, w0);
                    const ull wp1 = pack2(w1, w1);
                    const ull wp2 = pack2(w2, w2);
                    const ull wp3 = pack2(w3, w3);
                    const float* hrow = hs + (koff + kk) * HSTRIDE;
#pragma unroll
                    for (int bq = 0; bq < 4; ++bq) {
                        const ulonglong2 h2 = *(const ulonglong2*)(hrow + bq * 4);
                        const int i0 = (2 * bq) * 4;
                        const int i1 = (2 * bq + 1) * 4;
                        acc[i0+0] = fma2(wp0, h2.x, acc[i0+0]);
                        acc[i0+1] = fma2(wp1, h2.x, acc[i0+1]);
                        acc[i0+2] = fma2(wp2, h2.x, acc[i0+2]);
                        acc[i0+3] = fma2(wp3, h2.x, acc[i0+3]);
                        acc[i1+0] = fma2(wp0, h2.y, acc[i1+0]);
                        acc[i1+1] = fma2(wp1, h2.y, acc[i1+1]);
                        acc[i1+2] = fma2(wp2, h2.y, acc[i1+2]);
                        acc[i1+3] = fma2(wp3, h2.y, acc[i1+3]);
                    }
                }
            }
        }

#pragma unroll
        for (int s = 0; s < 5; ++s) {
            const int off = 16 >> s;
            const int n   = 16 >> s;
            const bool hi = (lane & off) != 0;
#pragma unroll
            for (int i = 0; i < n; ++i) {
                ull send = hi ? acc[i] : acc[i + n];
                ull r = __shfl_xor_sync(0xffffffffu, send, off);
                acc[i] = add2(hi ? acc[i + n] : acc[i], r);
            }
        }

        if (kh == 1) comb[wc * 32 + lane] = acc[0];
        __syncthreads();
        ull tot = acc[0];
        if (kh == 0) tot = add2(tot, comb[wc * 32 + lane]);

        const int srcl = (lane >> 1) * 4;
        const ull r0 = __shfl_sync(0xffffffffu, tot, srcl + 0);
        const ull r1 = __shfl_sync(0xffffffffu, tot, srcl + 1);
        const ull r2 = __shfl_sync(0xffffffffu, tot, srcl + 2);
        const ull r3 = __shfl_sync(0xffffffffu, tot, srcl + 3);

        if (kh == 0 && lane < B_) {
            const bool oddb = (lane & 1) != 0;
            const float2 p0 = unpack2(r0), p1 = unpack2(r1), p2 = unpack2(r2), p3 = unpack2(r3);
            const float gi = (oddb ? p0.y : p0.x) + xgi;
            const float gf = (oddb ? p1.y : p1.x) + xgf;
            const float gg = (oddb ? p2.y : p2.x) + xgg;
            const float go = (oddb ? p3.y : p3.x) + xgo;
            const float cn = sigf(gf) * creg + sigf(gi) * tanhf(gg);
            creg = cn;
            const float hn = sigf(go) * tanhf(cn);
            // int8 hi/lo quantization, fixed scale 1/127 (|h| < 1)
            const float hq = hn * 127.f;
            const float ih = rintf(hq);
            yh[orow * CD_ + cell] = (s8)ih;
            yl[orow * CD_ + cell] = (s8)rintf((hq - ih) * 128.f);
            hT[cell * B_ + lane]  = hn;
        }

        __threadfence();
        __syncthreads();
        if (tid == 0) {
            ull x = atomicAdd(&g_bar, 1ULL);
            ull target = x - (x % G) + G;
            while (*(volatile ull*)&g_bar < target) { }
        }
        __syncthreads();
    }
}

// ---------------- ilens tail ----------------
__global__ void write_tail_kernel(float* __restrict__ out, const int* __restrict__ ilens,
                                  long long base, long long out_size) {
    int i = threadIdx.x;
    if (i < B_ && base + i < out_size) out[base + i] = (float)ilens[i];
}

// ---------------- launch ----------------
extern "C" void kernel_launch(void* const* d_in, const int* in_sizes, int n_in,
                              void* d_out, int out_size)
{
    const float* xpad  = (const float*)d_in[0];   // [B,T,IDIM]
    const float* Wih0  = (const float*)d_in[1];   // [4096,320]
    const float* WihR  = (const float*)d_in[2];   // [3,4096,1024]
    const float* Whh   = (const float*)d_in[3];   // [4,4096,1024]
    const float* bih   = (const float*)d_in[4];   // [4,4096]
    const float* bhh   = (const float*)d_in[5];   // [4,4096]
    const float* Wlast = (const float*)d_in[6];   // [1024,1024]
    const float* blast = (const float*)d_in[7];   // [1024]
    const int*   ilens = (const int*)d_in[8];     // [16]
    float* out = (float*)d_out;

    float *xg, *hT, *sa, *sbv;
    s8 *qah, *qal, *qbh, *qbl;
    cudaGetSymbolAddress((void**)&xg,  g_xg);
    cudaGetSymbolAddress((void**)&hT,  g_hT);
    cudaGetSymbolAddress((void**)&qah, g_qah);
    cudaGetSymbolAddress((void**)&qal, g_qal);
    cudaGetSymbolAddress((void**)&qbh, g_qbh);
    cudaGetSymbolAddress((void**)&qbl, g_qbl);
    cudaGetSymbolAddress((void**)&sa,  g_sa);
    cudaGetSymbolAddress((void**)&sbv, g_sb);

    const int smem_step = CD_ * HSTRIDE * 4 + 8 * 32 * 8;
    cudaFuncSetAttribute(lstm_layer_kernel,
                         cudaFuncAttributeMaxDynamicSharedMemorySize, smem_step);
    cudaFuncSetAttribute(gemm_i8x3_kernel<0>,
                         cudaFuncAttributeMaxDynamicSharedMemorySize, GSMEM);
    cudaFuncSetAttribute(gemm_i8x3_kernel<1>,
                         cudaFuncAttributeMaxDynamicSharedMemorySize, GSMEM);

    const int M = B_ * T_;  // 8192

    for (int l = 0; l < LAYERS_; ++l) {
        const float* Bw = (l == 0) ? Wih0 : (WihR + (size_t)(l - 1) * GD_ * CD_);
        const int K = (l == 0) ? IDIM_ : CD_;

        if (l == 0)   // layers >=1: A-side quant written directly by lstm kernel
            quant_rows_kernel<<<M, 128>>>(xpad, qah, qal, sa, K);
        quant_rows_kernel<<<GD_, 128>>>(Bw, qbh, qbl, sbv, K);

        dim3 grid_xg(GD_ / 128, M / 128);
        gemm_i8x3_kernel<0><<<grid_xg, 256, GSMEM>>>(qah, qal, qbh, qbl, sa, sbv,
                                                     bih + l * GD_, bhh + l * GD_,
                                                     xg, M, GD_, K, ilens);

        const float* Wl = Whh + (size_t)l * GD_ * CD_;
        lstm_layer_kernel<<<NBLK_, 512, smem_step>>>(Wl, xg, qah, qal, hT);

        if (l == 0)   // switch A scale to fixed 1/127 for h layers + projection
            fill_sa_kernel<<<M / 256, 256>>>(sa);
    }

    // projection: dead rows (t >= ilens[b]) produce tanh(bias) in epilogue
    {
        quant_rows_kernel<<<HD_, 128>>>(Wlast, qbh, qbl, sbv, CD_);
        dim3 grid_p(HD_ / 128, M / 128);
        gemm_i8x3_kernel<1><<<grid_p, 256, GSMEM>>>(qah, qal, qbh, qbl, sa, sbv,
                                                    blast, nullptr,
                                                    out, M, HD_, CD_, ilens);
    }

    const long long base = (long long)B_ * T_ * HD_;  // 8388608
    if ((long long)out_size > base)
        write_tail_kernel<<<1, 32>>>(out, ilens, base, (long long)out_size);
}

// round 10
// speedup vs baseline: 1.2571x; 1.2571x over previous
#include <cuda_runtime.h>
#include <cuda_bf16.h>
#include <math.h>
#include <cstdint>

#define B_ 16
#define T_ 512
#define IDIM_ 320
#define CD_ 1024
#define GD_ 4096   // 4*CD
#define HD_ 1024
#define LAYERS_ 4
#define NBLK_ 128  // persistent grid: <= 148 SMs -> all co-resident

typedef unsigned long long ull;
typedef unsigned int uint;

// ---------------- scratch (static device globals; no runtime alloc) ----------------
__device__ float g_xg[(size_t)B_ * T_ * GD_];        // precomputed input gates
__device__ float g_x [(size_t)B_ * T_ * CD_];        // layer io buffer (ys)
__device__ float g_hT[CD_ * B_];                     // h transposed: hT[cell][b]
__device__ ull   g_bar;                              // ticket barrier (monotonic)
__device__ __align__(16) __nv_bfloat16 g_ah[(size_t)B_ * T_ * CD_]; // A hi
__device__ __align__(16) __nv_bfloat16 g_al[(size_t)B_ * T_ * CD_]; // A lo
__device__ __align__(16) __nv_bfloat16 g_bh[(size_t)GD_ * CD_];     // B hi
__device__ __align__(16) __nv_bfloat16 g_bl[(size_t)GD_ * CD_];     // B lo

// ---------------- packed fp32x2 helpers (step kernel) ----------------
__device__ __forceinline__ ull fma2(ull a, ull b, ull c) {
    ull d;
    asm("fma.rn.f32x2 %0, %1, %2, %3;" : "=l"(d) : "l"(a), "l"(b), "l"(c));
    return d;
}
__device__ __forceinline__ ull add2(ull a, ull b) {
    ull d;
    asm("add.rn.f32x2 %0, %1, %2;" : "=l"(d) : "l"(a), "l"(b));
    return d;
}
__device__ __forceinline__ ull pack2(float x, float y) {
    ull d;
    asm("mov.b64 %0, {%1, %2};" : "=l"(d) : "f"(x), "f"(y));
    return d;
}
__device__ __forceinline__ float2 unpack2(ull v) {
    float2 r;
    asm("mov.b64 {%0, %1}, %2;" : "=f"(r.x), "=f"(r.y) : "l"(v));
    return r;
}
__device__ __forceinline__ float sigf(float x) { return 1.f / (1.f + expf(-x)); }

#define HSTRIDE 20   // padded row stride (floats) for transposed h in smem

// ---------------- bf16 split conversion ----------------
// hi = bf16(x); lo = bf16(x - hi). Optional mask: zero rows with t >= ilens[b].
__global__ void __launch_bounds__(256) conv_split_kernel(
    const float* __restrict__ x, __nv_bfloat16* __restrict__ hi,
    __nv_bfloat16* __restrict__ lo, int n, int K, const int* __restrict__ ilens)
{
    int i = (blockIdx.x * 256 + threadIdx.x) * 2;
    if (i >= n) return;
    float2 v = *(const float2*)(x + i);
    if (ilens) {
        int m = i / K;
        int t = m & (T_ - 1);
        int b = m >> 9;
        if (t >= ilens[b]) { v.x = 0.f; v.y = 0.f; }
    }
    __nv_bfloat162 h2, l2;
    h2.x = __float2bfloat16_rn(v.x);
    h2.y = __float2bfloat16_rn(v.y);
    l2.x = __float2bfloat16_rn(v.x - __bfloat162float(h2.x));
    l2.y = __float2bfloat16_rn(v.y - __bfloat162float(h2.y));
    *(__nv_bfloat162*)(hi + i) = h2;
    *(__nv_bfloat162*)(lo + i) = l2;
}

// ---------------- MMA helpers ----------------
__device__ __forceinline__ void ldmx4(uint& r0, uint& r1, uint& r2, uint& r3,
                                      const __nv_bfloat16* p) {
    uint a = (uint)__cvta_generic_to_shared(p);
    asm volatile("ldmatrix.sync.aligned.m8n8.x4.shared.b16 {%0,%1,%2,%3}, [%4];"
                 : "=r"(r0), "=r"(r1), "=r"(r2), "=r"(r3) : "r"(a));
}
__device__ __forceinline__ void mma16816(float* d, const uint* a, uint b0, uint b1) {
    asm volatile(
        "mma.sync.aligned.m16n8k16.row.col.f32.bf16.bf16.f32 "
        "{%0,%1,%2,%3}, {%4,%5,%6,%7}, {%8,%9}, {%0,%1,%2,%3};"
        : "+f"(d[0]), "+f"(d[1]), "+f"(d[2]), "+f"(d[3])
        : "r"(a[0]), "r"(a[1]), "r"(a[2]), "r"(a[3]), "r"(b0), "r"(b1));
}

// ---------------- bf16x3 GEMM (NT): C = A*B^T + bias, fp32 accum ----------------
// R5-validated structure (pipe-capped): 128x128x32 tiles, 256 threads, 8 warps
// (4M x 2N, warp 32x64), register-prefetch ping-pong smem, ONE sync per slab.
// Virtual K'' = 3K over segments (Ah,Bh),(Al,Bh),(Ah,Bl).
// Dead tiles (t0 >= ilens[b]): TANH=0 return; TANH=1 skip mainloop -> tanh(bias).
#define SPAD 40  // bf16 row stride (32 + 8 pad): conflict-free ldmatrix phases
template <int TANH>
__global__ void __launch_bounds__(256) gemm_bf16x3_kernel(
    const __nv_bfloat16* __restrict__ Ah, const __nv_bfloat16* __restrict__ Al,
    const __nv_bfloat16* __restrict__ Bh, const __nv_bfloat16* __restrict__ Bl,
    const float* __restrict__ b1, const float* __restrict__ b2,
    float* __restrict__ C, int M, int N, int K, const int* __restrict__ ilens)
{
    __shared__ __align__(16) __nv_bfloat16 As[2][128][SPAD];
    __shared__ __align__(16) __nv_bfloat16 Bs[2][128][SPAD];

    const int tid  = threadIdx.x;
    const int m0   = blockIdx.y * 128;
    const int n0   = blockIdx.x * 128;
    const int srow = tid >> 1;           // staging: row 0..127
    const int scol = (tid & 1) * 16;     // staging: k offset 0 or 16
    const int lane = tid & 31;
    const int warp = tid >> 5;
    const int wm   = warp & 3;           // 4 warps along M (32 rows each)
    const int wn   = warp >> 2;          // 2 warps along N (64 cols each)

    const bool tdead = ((m0 & 511) >= __ldg(ilens + (m0 >> 9)));
    if (!TANH && tdead) return;

    const int perseg = K >> 5;           // slabs per segment
    const int nslab  = 3 * perseg;

    float acc[2][8][4];
#pragma unroll
    for (int i = 0; i < 2; ++i)
#pragma unroll
        for (int j = 0; j < 8; ++j)
#pragma unroll
            for (int q = 0; q < 4; ++q) acc[i][j][q] = 0.f;

    if (!tdead) {
        auto srcA = [&](int s) -> const uint4* {
            int seg = s / perseg, kin = (s - seg * perseg) * 32;
            const __nv_bfloat16* A = (seg == 1) ? Al : Ah;
            return (const uint4*)(A + (size_t)(m0 + srow) * K + kin + scol);
        };
        auto srcB = [&](int s) -> const uint4* {
            int seg = s / perseg, kin = (s - seg * perseg) * 32;
            const __nv_bfloat16* Bp = (seg == 2) ? Bl : Bh;
            return (const uint4*)(Bp + (size_t)(n0 + srow) * K + kin + scol);
        };

        // prologue: slab 0 -> buffer 0
        {
            const uint4* pa = srcA(0);
            const uint4* pb = srcB(0);
            uint4 a0 = pa[0], a1 = pa[1], bq0 = pb[0], bq1 = pb[1];
            *(uint4*)&As[0][srow][scol]     = a0;
            *(uint4*)&As[0][srow][scol + 8] = a1;
            *(uint4*)&Bs[0][srow][scol]     = bq0;
            *(uint4*)&Bs[0][srow][scol + 8] = bq1;
        }
        __syncthreads();

        for (int s = 0; s < nslab; ++s) {
            const int buf = s & 1;
            const bool has = (s + 1) < nslab;
            uint4 na0, na1, nb0, nb1;
            if (has) {
                const uint4* pa = srcA(s + 1);
                const uint4* pb = srcB(s + 1);
                na0 = pa[0]; na1 = pa[1]; nb0 = pb[0]; nb1 = pb[1];
            }

#pragma unroll
            for (int kh = 0; kh < 2; ++kh) {
                const int rq = lane & 15;
                const int cq = kh * 16 + ((lane >> 4) << 3);
                uint af[2][4];
#pragma unroll
                for (int mi = 0; mi < 2; ++mi)
                    ldmx4(af[mi][0], af[mi][1], af[mi][2], af[mi][3],
                          &As[buf][wm * 32 + mi * 16 + rq][cq]);
                uint bf4[4][4];
#pragma unroll
                for (int nq = 0; nq < 4; ++nq)
                    ldmx4(bf4[nq][0], bf4[nq][1], bf4[nq][2], bf4[nq][3],
                          &Bs[buf][wn * 64 + nq * 16 + rq][cq]);
#pragma unroll
                for (int mi = 0; mi < 2; ++mi)
#pragma unroll
                    for (int nq = 0; nq < 4; ++nq) {
                        mma16816(acc[mi][2 * nq],     af[mi], bf4[nq][0], bf4[nq][2]);
                        mma16816(acc[mi][2 * nq + 1], af[mi], bf4[nq][1], bf4[nq][3]);
                    }
            }

            if (has) {
                const int nb = buf ^ 1;
                *(uint4*)&As[nb][srow][scol]     = na0;
                *(uint4*)&As[nb][srow][scol + 8] = na1;
                *(uint4*)&Bs[nb][srow][scol]     = nb0;
                *(uint4*)&Bs[nb][srow][scol + 8] = nb1;
                __syncthreads();
            }
        }
    }

    // epilogue: lane l holds c[r + {0,8}][c + {0,1}], r = l>>2, c = 2*(l&3)
    // (masked/dead rows have acc = 0 -> TANH path yields tanh(bias) naturally)
    const int r  = lane >> 2;
    const int cq = (lane & 3) * 2;
#pragma unroll
    for (int mi = 0; mi < 2; ++mi) {
#pragma unroll
        for (int nj = 0; nj < 8; ++nj) {
            const int m1 = m0 + wm * 32 + mi * 16 + r;
            const int n1 = n0 + wn * 64 + nj * 8 + cq;
            float bb0 = b1 ? __ldg(b1 + n1) : 0.f;
            float bb1 = b1 ? __ldg(b1 + n1 + 1) : 0.f;
            if (b2) { bb0 += __ldg(b2 + n1); bb1 += __ldg(b2 + n1 + 1); }
            float v0 = acc[mi][nj][0] + bb0;
            float v1 = acc[mi][nj][1] + bb1;
            float v2 = acc[mi][nj][2] + bb0;
            float v3 = acc[mi][nj][3] + bb1;
            if (TANH) { v0 = tanhf(v0); v1 = tanhf(v1); v2 = tanhf(v2); v3 = tanhf(v3); }
            *(float2*)(C + (size_t)m1 * N + n1)       = make_float2(v0, v1);
            *(float2*)(C + (size_t)(m1 + 8) * N + n1) = make_float2(v2, v3);
        }
    }
}

// ---------------- persistent LSTM layer kernel (512 threads, k-split warps) ----------------
// R5-validated structure + batch-quad truncation: lanes hold ilens; per step
// live = popc(ballot(t < il)); fma nest runs 4 quads (live > 8) or 2 quads.
#define FMA_NEST(QN)                                                          \
    _Pragma("unroll 1")                                                       \
    for (int j = 0; j < 4; ++j) {                                             \
        const int kb = j * 128 + lane;                                        \
        _Pragma("unroll")                                                     \
        for (int kc = 0; kc < 4; ++kc) {                                      \
            const int kk = kb + kc * 32;                                      \
            const float w0 = __ldg(w0p + kk);                                 \
            const float w1 = __ldg(w1p + kk);                                 \
            const float w2 = __ldg(w2p + kk);                                 \
            const float w3 = __ldg(w3p + kk);                                 \
            const ull wp0 = pack2(w0, w0);                                    \
            const ull wp1 = pack2(w1, w1);                                    \
            const ull wp2 = pack2(w2, w2);                                    \
            const ull wp3 = pack2(w3, w3);                                    \
            const float* hrow = hs + (koff + kk) * HSTRIDE;                   \
            _Pragma("unroll")                                                 \
            for (int bq = 0; bq < (QN); ++bq) {                               \
                const ulonglong2 h2 = *(const ulonglong2*)(hrow + bq * 4);    \
                const int i0 = (2 * bq) * 4;                                  \
                const int i1 = (2 * bq + 1) * 4;                              \
                acc[i0+0] = fma2(wp0, h2.x, acc[i0+0]);                       \
                acc[i0+1] = fma2(wp1, h2.x, acc[i0+1]);                       \
                acc[i0+2] = fma2(wp2, h2.x, acc[i0+2]);                       \
                acc[i0+3] = fma2(wp3, h2.x, acc[i0+3]);                       \
                acc[i1+0] = fma2(wp0, h2.y, acc[i1+0]);                       \
                acc[i1+1] = fma2(wp1, h2.y, acc[i1+1]);                       \
                acc[i1+2] = fma2(wp2, h2.y, acc[i1+2]);                       \
                acc[i1+3] = fma2(wp3, h2.y, acc[i1+3]);                       \
            }                                                                 \
        }                                                                     \
    }

__global__ void __launch_bounds__(512) lstm_layer_kernel(
    const float* __restrict__ Whh,   // [4096,1024]
    const float* __restrict__ xg,    // [B*T,4096]
    float* __restrict__ ys,          // [B*T,1024]
    float* __restrict__ hT,          // [1024,16]
    const int* __restrict__ ilens)
{
    extern __shared__ float hs[];                    // [1024][HSTRIDE]
    ull* comb = (ull*)(hs + CD_ * HSTRIDE);          // [8*32] flat
    const int tid  = threadIdx.x;
    const int lane = tid & 31;
    const int warp = tid >> 5;                       // 0..15
    const int wc   = warp & 7;
    const int kh   = warp >> 3;
    const int cell = blockIdx.x * 8 + wc;
    const ull  G   = (ull)gridDim.x;

    const int koff = kh * 512;
    const float* w0p = Whh + (size_t)(0 * CD_ + cell) * CD_ + koff;
    const float* w1p = Whh + (size_t)(1 * CD_ + cell) * CD_ + koff;
    const float* w2p = Whh + (size_t)(2 * CD_ + cell) * CD_ + koff;
    const float* w3p = Whh + (size_t)(3 * CD_ + cell) * CD_ + koff;

    const int il_reg = (lane < B_) ? __ldg(ilens + lane) : 0;
    float creg = 0.f;

    for (int t = 0; t < T_; ++t) {
        const uint bal  = __ballot_sync(0xffffffffu, t < il_reg);
        const int  live = __popc(bal);               // live batches (>=1)
        const bool alive = (kh == 0) && (lane < B_) && (t < il_reg);

        float xgi = 0.f, xgf = 0.f, xgg = 0.f, xgo = 0.f;
        size_t orow = 0;
        if (alive) {
            orow = (size_t)(lane * T_ + t);
            const float* xr = xg + orow * GD_ + cell;
            xgi = __ldg(xr);
            xgf = __ldg(xr + CD_);
            xgg = __ldg(xr + 2 * CD_);
            xgo = __ldg(xr + 3 * CD_);
        }

        ull acc[32];
#pragma unroll
        for (int i = 0; i < 32; ++i) acc[i] = 0ULL;

        if (t > 0) {
            const int qn = (live > 8) ? 4 : 2;       // staged batch quads
            const float4* src = (const float4*)hT;
#pragma unroll 4
            for (int i = tid; i < CD_ * B_ / 4; i += 512) {
                if ((i & 3) < qn) {
                    float4 v = __ldcg(src + i);
                    const int k  = i >> 2;
                    const int bq = (i & 3) * 4;
                    float* d = hs + k * HSTRIDE + bq;
                    d[0] = v.x; d[1] = v.y; d[2] = v.z; d[3] = v.w;
                }
            }
            __syncthreads();

            if (live > 8) { FMA_NEST(4) } else { FMA_NEST(2) }
        }

#pragma unroll
        for (int s = 0; s < 5; ++s) {
            const int off = 16 >> s;
            const int n   = 16 >> s;
            const bool hi = (lane & off) != 0;
#pragma unroll
            for (int i = 0; i < n; ++i) {
                ull send = hi ? acc[i] : acc[i + n];
                ull r = __shfl_xor_sync(0xffffffffu, send, off);
                acc[i] = add2(hi ? acc[i + n] : acc[i], r);
            }
        }

        if (kh == 1) comb[wc * 32 + lane] = acc[0];
        __syncthreads();
        ull tot = acc[0];
        if (kh == 0) tot = add2(tot, comb[wc * 32 + lane]);

        const int srcl = (lane >> 1) * 4;
        const ull r0 = __shfl_sync(0xffffffffu, tot, srcl + 0);
        const ull r1 = __shfl_sync(0xffffffffu, tot, srcl + 1);
        const ull r2 = __shfl_sync(0xffffffffu, tot, srcl + 2);
        const ull r3 = __shfl_sync(0xffffffffu, tot, srcl + 3);

        if (alive) {
            const bool oddb = (lane & 1) != 0;
            const float2 p0 = unpack2(r0), p1 = unpack2(r1), p2 = unpack2(r2), p3 = unpack2(r3);
            const float gi = (oddb ? p0.y : p0.x) + xgi;
            const float gf = (oddb ? p1.y : p1.x) + xgf;
            const float gg = (oddb ? p2.y : p2.x) + xgg;
            const float go = (oddb ? p3.y : p3.x) + xgo;
            const float cn = sigf(gf) * creg + sigf(gi) * tanhf(gg);
            creg = cn;
            const float hn = sigf(go) * tanhf(cn);
            ys[orow * CD_ + cell] = hn;
            hT[cell * B_ + lane]  = hn;
        }

        // grid-wide ticket barrier (monotonic, replay-safe)
        __threadfence();
        __syncthreads();
        if (tid == 0) {
            ull x = atomicAdd(&g_bar, 1ULL);
            ull target = x - (x % G) + G;
            while (*(volatile ull*)&g_bar < target) { }
        }
        __syncthreads();
    }
}

// ---------------- ilens tail ----------------
__global__ void write_tail_kernel(float* __restrict__ out, const int* __restrict__ ilens,
                                  long long base, long long out_size) {
    int i = threadIdx.x;
    if (i < B_ && base + i < out_size) out[base + i] = (float)ilens[i];
}

// ---------------- launch ----------------
extern "C" void kernel_launch(void* const* d_in, const int* in_sizes, int n_in,
                              void* d_out, int out_size)
{
    const float* xpad  = (const float*)d_in[0];   // [B,T,IDIM]
    const float* Wih0  = (const float*)d_in[1];   // [4096,320]
    const float* WihR  = (const float*)d_in[2];   // [3,4096,1024]
    const float* Whh   = (const float*)d_in[3];   // [4,4096,1024]
    const float* bih   = (const float*)d_in[4];   // [4,4096]
    const float* bhh   = (const float*)d_in[5];   // [4,4096]
    const float* Wlast = (const float*)d_in[6];   // [1024,1024]
    const float* blast = (const float*)d_in[7];   // [1024]
    const int*   ilens = (const int*)d_in[8];     // [16]
    float* out = (float*)d_out;

    float *xg, *xb, *hT;
    __nv_bfloat16 *ah, *al, *bh, *bl;
    cudaGetSymbolAddress((void**)&xg, g_xg);
    cudaGetSymbolAddress((void**)&xb, g_x);
    cudaGetSymbolAddress((void**)&hT, g_hT);
    cudaGetSymbolAddress((void**)&ah, g_ah);
    cudaGetSymbolAddress((void**)&al, g_al);
    cudaGetSymbolAddress((void**)&bh, g_bh);
    cudaGetSymbolAddress((void**)&bl, g_bl);

    const int smem_step = CD_ * HSTRIDE * 4 + 8 * 32 * 8;  // 81920 + 2048
    cudaFuncSetAttribute(lstm_layer_kernel,
                         cudaFuncAttributeMaxDynamicSharedMemorySize, smem_step);

    const int M = B_ * T_;  // 8192

    for (int l = 0; l < LAYERS_; ++l) {
        const float* Ain = (l == 0) ? xpad : xb;
        const float* Bw  = (l == 0) ? Wih0 : (WihR + (size_t)(l - 1) * GD_ * CD_);
        const int K = (l == 0) ? IDIM_ : CD_;

        {
            int nA = M * K;
            conv_split_kernel<<<(nA / 2 + 255) / 256, 256>>>(Ain, ah, al, nA, K, nullptr);
            int nB = GD_ * K;
            conv_split_kernel<<<(nB / 2 + 255) / 256, 256>>>(Bw, bh, bl, nB, K, nullptr);
        }

        dim3 grid_xg(GD_ / 128, M / 128);
        gemm_bf16x3_kernel<0><<<grid_xg, 256>>>(ah, al, bh, bl,
                                                bih + l * GD_, bhh + l * GD_,
                                                xg, M, GD_, K, ilens);

        const float* Wl = Whh + (size_t)l * GD_ * CD_;
        lstm_layer_kernel<<<NBLK_, 512, smem_step>>>(Wl, xg, xb, hT, ilens);
    }

    // projection: conv masks dead rows (acc=0 -> tanh(bias)); dead tiles skip mainloop
    {
        int nA = M * CD_;
        conv_split_kernel<<<(nA / 2 + 255) / 256, 256>>>(xb, ah, al, nA, CD_, ilens);
        int nB = HD_ * CD_;
        conv_split_kernel<<<(nB / 2 + 255) / 256, 256>>>(Wlast, bh, bl, nB, CD_, nullptr);
        dim3 grid_p(HD_ / 128, M / 128);
        gemm_bf16x3_kernel<1><<<grid_p, 256>>>(ah, al, bh, bl, blast, nullptr,
                                               out, M, HD_, CD_, ilens);
    }

    const long long base = (long long)B_ * T_ * HD_;  // 8388608
    if ((long long)out_size > base)
        write_tail_kernel<<<1, 32>>>(out, ilens, base, (long long)out_size);
}